// round 17
// baseline (speedup 1.0000x reference)
#include <cuda_runtime.h>
#include <math.h>

#define NBOX 256

#define PLANE0 6400   // 80*80
#define PLANE1 1600   // 40*40
#define PLANE2 400    // 20*20
#define MOFF0 0
#define MOFF1 (16*PLANE0)            // 102400
#define MOFF2 (MOFF1 + 16*PLANE1)    // 128000
#define MTOT  (MOFF2 + 16*PLANE2)    // 134400

// stream tiles: every thread streams CCHUNK=8 float4 pairs (256B)
#define CCHUNK 8
#define TBLK0 1600
#define TBLK1 800
#define TBLK2 400
#define TILES (TBLK0 + TBLK1 + TBLK2)   // 2800

#define GRID 560          // persistent blocks; 560*5 = 2800 (perfect balance)
#define TPB  5            // tiles per block

#define CH 24             // boxes per smem chunk in phase 2

// Device state. Monotonic counters (g_arrive/g_done2) never reset —
// replay-safe via modular epoch math. g_acc/g_sse/g_summ are zero at load
// and restored to zero by this kernel every launch.
__device__ __align__(16) float g_acc[MTOT];   // per-pixel sum_c (p-t)^2
__device__ double g_sse[3];
__device__ double g_summ[3];
__device__ unsigned int g_arrive;
__device__ unsigned int g_done2;

// ---------------------------------------------------------------------------
// dual block reduction over 256 threads
__device__ __forceinline__ void block_reduce_sum2(float& a, float& b, float* sh) {
    #pragma unroll
    for (int off = 16; off > 0; off >>= 1) {
        a += __shfl_down_sync(0xffffffffu, a, off);
        b += __shfl_down_sync(0xffffffffu, b, off);
    }
    int lane = threadIdx.x & 31;
    int wid  = threadIdx.x >> 5;
    if (lane == 0) { sh[wid] = a; sh[8 + wid] = b; }
    __syncthreads();
    if (wid == 0) {
        a = (lane < 8) ? sh[lane] : 0.0f;
        b = (lane < 8) ? sh[8 + lane] : 0.0f;
        #pragma unroll
        for (int off = 4; off > 0; off >>= 1) {
            a += __shfl_down_sync(0xffffffffu, a, off);
            b += __shfl_down_sync(0xffffffffu, b, off);
        }
    }
}

// ---------------------------------------------------------------------------
// One stream tile (identical to the proven 33.9us/70% layout): thread owns a
// fixed (b, j4) float4 of pixels, streams CCHUNK channels of p/t with batched
// loads, REDs 4 per-component partials of sum_c (p-t)^2 into g_acc.
template<int C, int S, int MOFF>
__device__ __forceinline__ void stream_tile(const float4* __restrict__ p,
                                            const float4* __restrict__ t,
                                            int blk) {
    constexpr int PLANE4 = S * S / 4;
    constexpr int nsplit = C / CCHUNK;
    constexpr int per_b  = PLANE4 * nsplit;
    int idx = blk * 256 + threadIdx.x;
    int b  = idx / per_b;
    int r  = idx - b * per_b;
    int sp = r / PLANE4;
    int j  = r - sp * PLANE4;

    int base = (b * C + sp * CCHUNK) * PLANE4 + j;

    float4 pv[4], tv[4];
    #pragma unroll
    for (int u = 0; u < 4; u++) pv[u] = __ldcs(p + base + u * PLANE4);
    #pragma unroll
    for (int u = 0; u < 4; u++) tv[u] = __ldcs(t + base + u * PLANE4);

    float a0 = 0.0f, a1 = 0.0f, a2 = 0.0f, a3 = 0.0f;
    #pragma unroll
    for (int cc = 0; cc < CCHUNK; cc += 4) {
        if (cc > 0) {
            base += 4 * PLANE4;
            #pragma unroll
            for (int u = 0; u < 4; u++) pv[u] = __ldcs(p + base + u * PLANE4);
            #pragma unroll
            for (int u = 0; u < 4; u++) tv[u] = __ldcs(t + base + u * PLANE4);
        }
        #pragma unroll
        for (int u = 0; u < 4; u++) {
            float d0 = pv[u].x - tv[u].x;
            float d1 = pv[u].y - tv[u].y;
            float d2 = pv[u].z - tv[u].z;
            float d3 = pv[u].w - tv[u].w;
            a0 += d0 * d0; a1 += d1 * d1; a2 += d2 * d2; a3 += d3 * d3;
        }
    }

    float* dst = g_acc + MOFF + ((b * PLANE4 + j) << 2);
    atomicAdd(dst + 0, a0);
    atomicAdd(dst + 1, a1);
    atomicAdd(dst + 2, a2);
    atomicAdd(dst + 3, a3);
}

// ---------------------------------------------------------------------------
__global__ void __launch_bounds__(256, 4)
fused_persistent(const float4* __restrict__ p0, const float4* __restrict__ t0,
                 const float4* __restrict__ p1, const float4* __restrict__ t1,
                 const float4* __restrict__ p2, const float4* __restrict__ t2,
                 const float* __restrict__ bboxes, const int* __restrict__ bidx,
                 float* __restrict__ out) {
    // Phase-2 shared state (must total < 48KB static)
    __shared__ float s_plane[PLANE0];      // 25.6 KB
    __shared__ float s_ex[CH * 80];        // 7.7 KB
    __shared__ float s_ey[CH * 80];        // 7.7 KB
    __shared__ float s_prm[CH][8];
    __shared__ int   s_list[NBOX];
    __shared__ int   s_cnt;
    __shared__ float s_red[16];

    int tid = threadIdx.x;

    // ---------------- Phase 1: stream (5 tiles per block, perfect balance)
    {
        int t0i = blockIdx.x * TPB;
        #pragma unroll
        for (int i = 0; i < TPB; i++) {
            int tl = t0i + i;
            if (tl < TBLK0)               stream_tile<128, 80, MOFF0>(p0, t0, tl);
            else if (tl < TBLK0 + TBLK1)  stream_tile<256, 40, MOFF1>(p1, t1, tl - TBLK0);
            else                          stream_tile<512, 20, MOFF2>(p2, t2, tl - TBLK0 - TBLK1);
        }
    }

    // ---------------- Grid barrier (monotonic epoch counter; no reset needed
    // because graph replays of this kernel are serialized on one stream).
    {
        __threadfence();
        __syncthreads();
        if (tid == 0) {
            unsigned int v = atomicAdd(&g_arrive, 1u);
            unsigned int target = (v / GRID + 1u) * GRID;
            while (*((volatile unsigned int*)&g_arrive) < target)
                __nanosleep(128);
        }
        __syncthreads();
        __threadfence();
    }

    // ---------------- Phase 2: mask + apply (48 blocks; others exit)
    int rb = blockIdx.x;
    if (rb >= 48) return;
    int level = rb >> 4;          // 0..2
    int b     = rb & 15;
    int S     = 80 >> level;
    int plane = S * S;
    int moff  = (level == 0) ? MOFF0 : (level == 1) ? MOFF1 : MOFF2;

    if (tid == 0) s_cnt = 0;
    __syncthreads();
    if (bidx[tid] == b) {
        int slot = atomicAdd(&s_cnt, 1);
        s_list[slot] = tid;
    }
    for (int i = tid; i < plane; i += 256) s_plane[i] = 0.0f;
    __syncthreads();
    int cnt = s_cnt;

    // build mask in smem: chunks of CH boxes, separable tables
    // (denom = STD^2*(w/2)^2 = w^2 for STD=2; gauss = exp(-tx)*exp(-ty))
    for (int c0 = 0; c0 < cnt; c0 += CH) {
        int ch = min(CH, cnt - c0);
        if (tid < ch) {
            float4 bb = reinterpret_cast<const float4*>(bboxes)[s_list[c0 + tid]];
            float fS = (float)S;
            int S1 = S - 1;
            int xc = (int)floorf(bb.x * fS);
            int yc = (int)floorf(bb.y * fS);
            int w  = (int)floorf(bb.z * fS);
            int h  = (int)floorf(bb.w * fS);
            int xl = max(xc - w / 2, 0);
            int xr = min(xc + w / 2, S1);
            int yt = max(yc - h / 2, 0);
            int yd = min(yc + h / 2, S1);
            s_prm[tid][0] = (float)xc;
            s_prm[tid][1] = (float)yc;
            s_prm[tid][2] = (float)(xr - xl + 1);
            s_prm[tid][3] = (float)(yd - yt + 1);
            s_prm[tid][4] = (float)xl;
            s_prm[tid][5] = (float)xr;
            s_prm[tid][6] = (float)yt;
            s_prm[tid][7] = (float)yd;
        }
        __syncthreads();
        for (int i = tid; i < ch * S; i += 256) {
            int k = i / S;
            int x = i - k * S;
            float fx = (float)x;
            float dx = fx - s_prm[k][0];
            float dy = fx - s_prm[k][1];
            float wd = s_prm[k][2];
            float ht = s_prm[k][3];
            s_ex[k * S + x] = (fx >= s_prm[k][4] && fx <= s_prm[k][5])
                              ? expf(-(dx * dx) / (wd * wd)) : 0.0f;
            s_ey[k * S + x] = (fx >= s_prm[k][6] && fx <= s_prm[k][7])
                              ? expf(-(dy * dy) / (ht * ht)) : 0.0f;
        }
        __syncthreads();
        int plane4 = plane >> 2;
        for (int i4 = tid; i4 < plane4; i4 += 256) {
            int pix = i4 * 4;
            int y   = pix / S;
            int x0  = pix - y * S;
            float4 mp = reinterpret_cast<float4*>(s_plane)[i4];
            for (int k = 0; k < ch; k++) {
                float4 exv = *reinterpret_cast<float4*>(&s_ex[k * S + x0]);
                float  eyv = s_ey[k * S + y];
                mp.x = fmaxf(mp.x, exv.x * eyv);
                mp.y = fmaxf(mp.y, exv.y * eyv);
                mp.z = fmaxf(mp.z, exv.z * eyv);
                mp.w = fmaxf(mp.w, exv.w * eyv);
            }
            reinterpret_cast<float4*>(s_plane)[i4] = mp;
        }
        __syncthreads();
    }

    // apply: sse += m^2 * acc, summ += m; zero g_acc for next replay
    float se = 0.0f, sm = 0.0f;
    {
        float* ga = g_acc + moff + b * plane;
        for (int i = tid; i < plane; i += 256) {
            float m = s_plane[i];
            float a = ga[i];
            ga[i] = 0.0f;
            se += m * m * a;
            sm += m;
        }
    }
    block_reduce_sum2(se, sm, s_red);
    if (tid == 0) {
        atomicAdd(&g_sse[level],  (double)se);
        atomicAdd(&g_summ[level], (double)sm);
        __threadfence();
        unsigned int v2 = atomicAdd(&g_done2, 1u);
        if ((v2 % 48u) == 47u) {   // last phase-2 block of this launch
            volatile double* sse_  = g_sse;
            volatile double* summ_ = g_summ;
            double tot = sse_[0] / (128.0 * summ_[0])
                       + sse_[1] / (256.0 * summ_[1])
                       + sse_[2] / (512.0 * summ_[2]);
            out[0] = (float)(tot / 3.0);
            #pragma unroll
            for (int l = 0; l < 3; l++) { g_sse[l] = 0.0; g_summ[l] = 0.0; }
        }
    }
}

// ---------------------------------------------------------------------------
extern "C" void kernel_launch(void* const* d_in, const int* in_sizes, int n_in,
                              void* d_out, int out_size) {
    // metadata order (interleaved): 0:y_pred0 1:y_true0 2:y_pred1 3:y_true1
    // 4:y_pred2 5:y_true2 6:bboxes 7:cls 8:batch_idx
    const float* p0 = (const float*)d_in[0];
    const float* t0 = (const float*)d_in[1];
    const float* p1 = (const float*)d_in[2];
    const float* t1 = (const float*)d_in[3];
    const float* p2 = (const float*)d_in[4];
    const float* t2 = (const float*)d_in[5];
    const float* bboxes = (const float*)d_in[6];
    const int*   bidx   = (const int*)d_in[8];
    float* out = (float*)d_out;

    fused_persistent<<<GRID, 256>>>((const float4*)p0, (const float4*)t0,
                                    (const float4*)p1, (const float4*)t1,
                                    (const float4*)p2, (const float4*)t2,
                                    bboxes, bidx, out);
}